// round 1
// baseline (speedup 1.0000x reference)
#include <cuda_runtime.h>
#include <math.h>

#define NPTS 100000
#define KNB  16
#define DIM  64
#define NK   (NPTS*KNB)

// ---------------- scratch (device globals: allocation-free rule) ----------------
__device__ float  g_q[NPTS*DIM];
__device__ float  g_k[NPTS*DIM];
__device__ float  g_v[NPTS*DIM];
__device__ float  g_wpre[(size_t)NPTS*KNB*DIM];   // 409.6 MB
__device__ double g_acc[256];    // [0:64)=sum1 [64:128)=sq1 [128:192)=sum2 [192:256)=sq2
__device__ float  g_stats[256];  // [0:64)=scale1 [64:128)=shift1 [128:192)=scale2 [192:256)=shift2

// ---------------- kernel 0: zero accumulators ----------------
__global__ void zero_acc_kernel() {
    if (threadIdx.x < 256) g_acc[threadIdx.x] = 0.0;
}

// ---------------- kernel 1: q/k/v linear layers ----------------
__global__ void qkv_kernel(const float* __restrict__ feats,
                           const float* __restrict__ qw, const float* __restrict__ qb,
                           const float* __restrict__ kw, const float* __restrict__ kb,
                           const float* __restrict__ vw, const float* __restrict__ vb)
{
    __shared__ __align__(16) float sWt[DIM*DIM];   // sWt[i*64+d] = W[d][i]
    __shared__ float sB[DIM];
    __shared__ __align__(16) float sF[4][DIM];

    const int sub = threadIdx.x >> 6;
    const int d   = threadIdx.x & 63;

    #pragma unroll
    for (int m = 0; m < 3; m++) {
        const float* W = (m == 0) ? qw : (m == 1) ? kw : vw;
        const float* B = (m == 0) ? qb : (m == 1) ? kb : vb;
        float*       O = (m == 0) ? g_q : (m == 1) ? g_k : g_v;

        __syncthreads();   // protect sWt/sB against previous matrix's readers
        for (int t = threadIdx.x; t < DIM*DIM; t += 256) {
            int dd = t & 63, i = t >> 6;
            sWt[t] = __ldg(W + dd*DIM + i);
        }
        if (threadIdx.x < DIM) sB[threadIdx.x] = __ldg(B + threadIdx.x);
        __syncthreads();

        for (int n0 = blockIdx.x*4; n0 < NPTS; n0 += gridDim.x*4) {
            int n = n0 + sub;
            __syncthreads();   // protect sF reuse
            if (n < NPTS) sF[sub][d] = __ldg(feats + n*DIM + d);
            __syncthreads();
            if (n < NPTS) {
                float acc = sB[d];
                #pragma unroll
                for (int i = 0; i < DIM; i += 4) {
                    float4 f = *(const float4*)&sF[sub][i];
                    acc = fmaf(f.x, sWt[(i  )*DIM + d], acc);
                    acc = fmaf(f.y, sWt[(i+1)*DIM + d], acc);
                    acc = fmaf(f.z, sWt[(i+2)*DIM + d], acc);
                    acc = fmaf(f.w, sWt[(i+3)*DIM + d], acc);
                }
                O[n*DIM + d] = acc;
            }
        }
    }
}

// ---------------- kernel 2: BN1 statistics over p_lin ----------------
__global__ void stats1_kernel(const float* __restrict__ points,
                              const int*   __restrict__ nb,
                              const float* __restrict__ pw,
                              const float* __restrict__ pb)
{
    const int sub = threadIdx.x >> 6;
    const int d   = threadIdx.x & 63;
    const float w0 = __ldg(pw + d*3    );
    const float w1 = __ldg(pw + d*3 + 1);
    const float w2 = __ldg(pw + d*3 + 2);
    const float b  = __ldg(pb + d);

    double s = 0.0, sq = 0.0;
    for (int it = blockIdx.x*4 + sub; it < NK; it += gridDim.x*4) {
        int idx = __ldg(nb + it);
        float x, y, z;
        if (idx >= NPTS) { x = y = z = 1e6f; }
        else {
            x = __ldg(points + idx*3    );
            y = __ldg(points + idx*3 + 1);
            z = __ldg(points + idx*3 + 2);
        }
        float v = fmaf(w2, z, fmaf(w1, y, fmaf(w0, x, b)));
        s  += (double)v;
        sq += (double)v * (double)v;
    }

    __shared__ double shred[256];
    shred[threadIdx.x] = s;  __syncthreads();
    if (threadIdx.x < 64)
        atomicAdd(&g_acc[d], shred[d] + shred[64+d] + shred[128+d] + shred[192+d]);
    __syncthreads();
    shred[threadIdx.x] = sq; __syncthreads();
    if (threadIdx.x < 64)
        atomicAdd(&g_acc[64+d], shred[d] + shred[64+d] + shred[128+d] + shred[192+d]);
}

// ---------------- kernel 3/5: finalize BN stats -> scale/shift ----------------
__global__ void finalize_kernel(const float* __restrict__ gamma,
                                const float* __restrict__ beta, int base)
{
    int d = threadIdx.x;
    if (d < 64) {
        double cnt = (double)NK;
        double m   = g_acc[base + d] / cnt;
        double var = g_acc[base + 64 + d] / cnt - m*m;
        double rs  = 1.0 / sqrt(var + 1e-5);
        double g   = (double)__ldg(gamma + d);
        g_stats[base + d]      = (float)(rs * g);
        g_stats[base + 64 + d] = (float)((double)__ldg(beta + d) - m * rs * g);
    }
}

// ---------------- kernel 4: pass C — gather, w_in, GEMM, store w_pre, BN2 stats ----------------
__global__ void passC_kernel(const float* __restrict__ points,
                             const int*   __restrict__ nb,
                             const float* __restrict__ pw,
                             const float* __restrict__ pb,
                             const float* __restrict__ ww,
                             const float* __restrict__ wb)
{
    __shared__ __align__(16) float sWt[DIM*DIM];          // sWt[e*64+d] = ww[d][e]
    __shared__ __align__(16) float sWin[4][KNB*DIM];
    __shared__ int   sIdx[4][KNB];
    __shared__ float sPts[4][KNB*4];
    __shared__ float sWb[DIM], sScale[DIM], sShift[DIM];

    for (int t = threadIdx.x; t < DIM*DIM; t += 256) {
        int dd = t & 63, e = t >> 6;
        sWt[t] = __ldg(ww + dd*DIM + e);
    }
    if (threadIdx.x < DIM) {
        sWb[threadIdx.x]    = __ldg(wb + threadIdx.x);
        sScale[threadIdx.x] = g_stats[threadIdx.x];
        sShift[threadIdx.x] = g_stats[64 + threadIdx.x];
    }
    __syncthreads();

    const int sub = threadIdx.x >> 6;
    const int d   = threadIdx.x & 63;
    const float w0 = __ldg(pw + d*3), w1 = __ldg(pw + d*3+1), w2 = __ldg(pw + d*3+2);
    const float pbd = __ldg(pb + d);
    const float sc1 = sScale[d], sh1 = sShift[d];

    double ds = 0.0, dsq = 0.0;

    for (int n0 = blockIdx.x*4; n0 < NPTS; n0 += gridDim.x*4) {
        int n = n0 + sub;
        bool act = (n < NPTS);
        __syncthreads();  // protect sWin/sIdx/sPts reuse
        if (act && d < KNB) sIdx[sub][d] = __ldg(nb + n*KNB + d);
        __syncthreads();
        if (act && d < 48) {
            int k = d / 3, c = d % 3;
            int idx = sIdx[sub][k];
            sPts[sub][k*4 + c] = (idx >= NPTS) ? 1e6f : __ldg(points + idx*3 + c);
        }
        __syncthreads();
        if (act) {
            float qd = g_q[n*DIM + d];
            #pragma unroll
            for (int k = 0; k < KNB; k++) {
                int idx = sIdx[sub][k];
                float x = sPts[sub][k*4], y = sPts[sub][k*4+1], z = sPts[sub][k*4+2];
                float pl = fmaf(w2, z, fmaf(w1, y, fmaf(w0, x, pbd)));
                float pf = fmaxf(fmaf(pl, sc1, sh1), 0.f);
                float kg = (idx >= NPTS) ? 0.f : g_k[idx*DIM + d];
                sWin[sub][k*DIM + d] = fmaf(kg, qd, pf);
            }
        }
        __syncthreads();
        if (act) {
            float acc[KNB];
            float bb = sWb[d];
            #pragma unroll
            for (int k = 0; k < KNB; k++) acc[k] = bb;
            #pragma unroll
            for (int e = 0; e < DIM; e += 4) {
                float wa = sWt[(e  )*DIM + d];
                float wbv= sWt[(e+1)*DIM + d];
                float wc = sWt[(e+2)*DIM + d];
                float wd = sWt[(e+3)*DIM + d];
                #pragma unroll
                for (int k = 0; k < KNB; k++) {
                    float4 a = *(const float4*)&sWin[sub][k*DIM + e];
                    acc[k] = fmaf(a.x, wa, fmaf(a.y, wbv, fmaf(a.z, wc, fmaf(a.w, wd, acc[k]))));
                }
            }
            float ls = 0.f, lsq = 0.f;
            #pragma unroll
            for (int k = 0; k < KNB; k++) {
                float v = acc[k];
                g_wpre[((size_t)n*KNB + k)*DIM + d] = v;
                ls += v;
                lsq = fmaf(v, v, lsq);
            }
            ds  += (double)ls;
            dsq += (double)lsq;
        }
    }

    __shared__ double shred[256];
    __syncthreads();
    shred[threadIdx.x] = ds;  __syncthreads();
    if (threadIdx.x < 64)
        atomicAdd(&g_acc[128 + d], shred[d] + shred[64+d] + shred[128+d] + shred[192+d]);
    __syncthreads();
    shred[threadIdx.x] = dsq; __syncthreads();
    if (threadIdx.x < 64)
        atomicAdd(&g_acc[192 + d], shred[d] + shred[64+d] + shred[128+d] + shred[192+d]);
}

// ---------------- kernel 6: pass D — BN2 + softmax + weighted sum ----------------
__global__ void passD_kernel(const float* __restrict__ points,
                             const int*   __restrict__ nb,
                             const float* __restrict__ pw,
                             const float* __restrict__ pb,
                             float* __restrict__ out)
{
    __shared__ int   sIdx[4][KNB];
    __shared__ float sPts[4][KNB*4];

    const int sub = threadIdx.x >> 6;
    const int d   = threadIdx.x & 63;
    const float w0 = __ldg(pw + d*3), w1 = __ldg(pw + d*3+1), w2 = __ldg(pw + d*3+2);
    const float pbd = __ldg(pb + d);
    const float sc1 = g_stats[d],       sh1 = g_stats[64 + d];
    const float sc2 = g_stats[128 + d], sh2 = g_stats[192 + d];

    for (int n0 = blockIdx.x*4; n0 < NPTS; n0 += gridDim.x*4) {
        int n = n0 + sub;
        bool act = (n < NPTS);
        __syncthreads();
        if (act && d < KNB) sIdx[sub][d] = __ldg(nb + n*KNB + d);
        __syncthreads();
        if (act && d < 48) {
            int k = d / 3, c = d % 3;
            int idx = sIdx[sub][k];
            sPts[sub][k*4 + c] = (idx >= NPTS) ? 1e6f : __ldg(points + idx*3 + c);
        }
        __syncthreads();
        if (act) {
            float wp[KNB];
            float mx = -1e30f;
            #pragma unroll
            for (int k = 0; k < KNB; k++) {
                float v = g_wpre[((size_t)n*KNB + k)*DIM + d];
                v = fmaxf(fmaf(v, sc2, sh2), 0.f);
                wp[k] = v;
                mx = fmaxf(mx, v);
            }
            float ssum = 0.f;
            #pragma unroll
            for (int k = 0; k < KNB; k++) {
                float e = __expf(wp[k] - mx);
                wp[k] = e;
                ssum += e;
            }
            float inv = 1.f / ssum;
            float att = 0.f;
            #pragma unroll
            for (int k = 0; k < KNB; k++) {
                int idx = sIdx[sub][k];
                float x = sPts[sub][k*4], y = sPts[sub][k*4+1], z = sPts[sub][k*4+2];
                float pl = fmaf(w2, z, fmaf(w1, y, fmaf(w0, x, pbd)));
                float pf = fmaxf(fmaf(pl, sc1, sh1), 0.f);
                float vg = (idx >= NPTS) ? 0.f : g_v[idx*DIM + d];
                att = fmaf(vg + pf, wp[k] * inv, att);
            }
            out[n*DIM + d] = att;
        }
    }
}

// ---------------- launch ----------------
extern "C" void kernel_launch(void* const* d_in, const int* in_sizes, int n_in,
                              void* d_out, int out_size)
{
    const float* points  = (const float*)d_in[0];
    const int*   nbrs    = (const int*)  d_in[1];
    const float* feats   = (const float*)d_in[2];
    const float* q_w = (const float*)d_in[3];  const float* q_b = (const float*)d_in[4];
    const float* k_w = (const float*)d_in[5];  const float* k_b = (const float*)d_in[6];
    const float* v_w = (const float*)d_in[7];  const float* v_b = (const float*)d_in[8];
    const float* p_w = (const float*)d_in[9];  const float* p_b = (const float*)d_in[10];
    const float* p_gamma = (const float*)d_in[11]; const float* p_beta = (const float*)d_in[12];
    const float* w_w = (const float*)d_in[13]; const float* w_b = (const float*)d_in[14];
    const float* w_gamma = (const float*)d_in[15]; const float* w_beta = (const float*)d_in[16];
    float* out = (float*)d_out;

    zero_acc_kernel<<<1, 256>>>();
    qkv_kernel<<<592, 256>>>(feats, q_w, q_b, k_w, k_b, v_w, v_b);
    stats1_kernel<<<592, 256>>>(points, nbrs, p_w, p_b);
    finalize_kernel<<<1, 64>>>(p_gamma, p_beta, 0);
    passC_kernel<<<1184, 256>>>(points, nbrs, p_w, p_b, w_w, w_b);
    finalize_kernel<<<1, 64>>>(w_gamma, w_beta, 128);
    passD_kernel<<<592, 256>>>(points, nbrs, p_w, p_b, out);
}

// round 2
// speedup vs baseline: 1.9480x; 1.9480x over previous
#include <cuda_runtime.h>
#include <math.h>

#define NPTS 100000
#define KNB  16
#define DIM  64
#define NK   (NPTS*KNB)

// ---------------- scratch ----------------
__device__ float  g_q[(size_t)NPTS*DIM];
__device__ float  g_k[(size_t)NPTS*DIM];
__device__ float  g_v[(size_t)NPTS*DIM];
__device__ float  g_wpre[(size_t)NPTS*KNB*DIM];   // 409.6 MB
__device__ double g_acc[256];    // [0:64)=sum1 [64:128)=sq1 [128:192)=sum2 [192:256)=sq2
__device__ float  g_stats[256];  // [0:64)=scale1 [64:128)=shift1 [128:192)=scale2 [192:256)=shift2

__global__ void zero_acc_kernel() {
    if (threadIdx.x < 256) g_acc[threadIdx.x] = 0.0;
}

// ---------------- kernel 1: fused q/k/v GEMM (64 -> 192 channels) ----------------
// dyn smem: sW[64*192] (transposed weights), sF[64*20] (transposed feats, pad 20), sB[192]
#define QKV_THREADS 192
__global__ void __launch_bounds__(QKV_THREADS) qkv_kernel(
    const float* __restrict__ feats,
    const float* __restrict__ qw, const float* __restrict__ qb,
    const float* __restrict__ kw, const float* __restrict__ kb,
    const float* __restrict__ vw, const float* __restrict__ vb)
{
    extern __shared__ float sm[];
    float* sW = sm;             // 12288 floats: sW[e*192 + c] = W_c[c][e]
    float* sF = sm + 12288;     // 64*20:        sF[e*20 + p]  = feats[n0+p][e]
    float* sB = sm + 12288 + 1280;  // 192

    const int tid = threadIdx.x;
    for (int i = tid; i < 192*64; i += QKV_THREADS) {
        int c = i % 192, e = i / 192;
        const float* src = (c < 64) ? qw : (c < 128) ? kw : vw;
        sW[e*192 + c] = __ldg(src + (c & 63)*DIM + e);
    }
    if (tid < 192) {
        const float* src = (tid < 64) ? qb : (tid < 128) ? kb : vb;
        sB[tid] = __ldg(src + (tid & 63));
    }
    __syncthreads();

    const int c4 = tid % 48;        // channel quad
    const int pb = tid / 48;        // point quad (0..3)
    const float4 b4 = *(const float4*)&sB[4*c4];
    const int c = 4*c4;

    for (int tile = blockIdx.x; tile < NPTS/16; tile += gridDim.x) {
        const int n0 = tile*16;
        __syncthreads();
        for (int i = tid; i < 16*64; i += QKV_THREADS) {
            int p = i >> 6, e = i & 63;
            sF[e*20 + p] = __ldg(feats + (size_t)(n0+p)*DIM + e);
        }
        __syncthreads();

        float4 a0 = b4, a1 = b4, a2 = b4, a3 = b4;
        #pragma unroll 8
        for (int e = 0; e < 64; e++) {
            float4 w4 = *(const float4*)&sW[e*192 + c];
            float4 f4 = *(const float4*)&sF[e*20 + 4*pb];
            a0.x = fmaf(f4.x, w4.x, a0.x); a0.y = fmaf(f4.x, w4.y, a0.y);
            a0.z = fmaf(f4.x, w4.z, a0.z); a0.w = fmaf(f4.x, w4.w, a0.w);
            a1.x = fmaf(f4.y, w4.x, a1.x); a1.y = fmaf(f4.y, w4.y, a1.y);
            a1.z = fmaf(f4.y, w4.z, a1.z); a1.w = fmaf(f4.y, w4.w, a1.w);
            a2.x = fmaf(f4.z, w4.x, a2.x); a2.y = fmaf(f4.z, w4.y, a2.y);
            a2.z = fmaf(f4.z, w4.z, a2.z); a2.w = fmaf(f4.z, w4.w, a2.w);
            a3.x = fmaf(f4.w, w4.x, a3.x); a3.y = fmaf(f4.w, w4.y, a3.y);
            a3.z = fmaf(f4.w, w4.z, a3.z); a3.w = fmaf(f4.w, w4.w, a3.w);
        }

        float* dst = (c < 64) ? g_q : (c < 128) ? g_k : g_v;
        const int cc = c & 63;
        const int nb0 = n0 + 4*pb;
        *(float4*)(dst + (size_t)(nb0+0)*DIM + cc) = a0;
        *(float4*)(dst + (size_t)(nb0+1)*DIM + cc) = a1;
        *(float4*)(dst + (size_t)(nb0+2)*DIM + cc) = a2;
        *(float4*)(dst + (size_t)(nb0+3)*DIM + cc) = a3;
    }
}

// ---------------- kernel 2: BN1 statistics over p_lin ----------------
__global__ void __launch_bounds__(256) stats1_kernel(
    const float* __restrict__ points,
    const int*   __restrict__ nb,
    const float* __restrict__ pw,
    const float* __restrict__ pb)
{
    const int tid  = threadIdx.x;
    const int quad = tid & 15;          // channel quad
    const int slot = tid >> 4;          // row slot (0..15)
    const int d0   = 4*quad;

    float w[12], br[4];
    #pragma unroll
    for (int j = 0; j < 4; j++) {
        w[j*3+0] = __ldg(pw + (d0+j)*3 + 0);
        w[j*3+1] = __ldg(pw + (d0+j)*3 + 1);
        w[j*3+2] = __ldg(pw + (d0+j)*3 + 2);
        br[j]    = __ldg(pb + d0 + j);
    }

    float s[4] = {0,0,0,0}, sq[4] = {0,0,0,0};
    for (int r = blockIdx.x*16 + slot; r < NK; r += gridDim.x*16) {
        int idx = __ldg(nb + r);
        float x, y, z;
        if (idx >= NPTS) { x = y = z = 1e6f; }
        else {
            x = __ldg(points + (size_t)idx*3    );
            y = __ldg(points + (size_t)idx*3 + 1);
            z = __ldg(points + (size_t)idx*3 + 2);
        }
        #pragma unroll
        for (int j = 0; j < 4; j++) {
            float v = fmaf(w[j*3+2], z, fmaf(w[j*3+1], y, fmaf(w[j*3+0], x, br[j])));
            s[j] += v;
            sq[j] = fmaf(v, v, sq[j]);
        }
    }

    __shared__ float sred[256*8];
    #pragma unroll
    for (int j = 0; j < 4; j++) {
        sred[tid*8 + j]     = s[j];
        sred[tid*8 + 4 + j] = sq[j];
    }
    __syncthreads();
    if (tid < 64) {
        int tq = tid >> 2, j = tid & 3;
        double ds = 0.0, dsq = 0.0;
        #pragma unroll
        for (int sl = 0; sl < 16; sl++) {
            ds  += (double)sred[(sl*16 + tq)*8 + j];
            dsq += (double)sred[(sl*16 + tq)*8 + 4 + j];
        }
        atomicAdd(&g_acc[tid],      ds);
        atomicAdd(&g_acc[64 + tid], dsq);
    }
}

// ---------------- kernel 3/5: finalize ----------------
__global__ void finalize_kernel(const float* __restrict__ gamma,
                                const float* __restrict__ beta, int base)
{
    int d = threadIdx.x;
    if (d < 64) {
        double cnt = (double)NK;
        double m   = g_acc[base + d] / cnt;
        double var = g_acc[base + 64 + d] / cnt - m*m;
        double rs  = 1.0 / sqrt(var + 1e-5);
        double g   = (double)__ldg(gamma + d);
        g_stats[base + d]      = (float)(rs * g);
        g_stats[base + 64 + d] = (float)((double)__ldg(beta + d) - m * rs * g);
    }
}

// ---------------- kernel 4: pass C ----------------
// 128 threads, 8 points per iter. t = tid&15 owns d0=4t. T_k=16 x T_d=4 register tile.
// dyn smem: sWt[64*64] + sWin[8*16*16 float4] + sIdx[128] + sPts[8*16*4] + sWb[64]
__global__ void __launch_bounds__(128, 4) passC_kernel(
    const float* __restrict__ points,
    const int*   __restrict__ nb,
    const float* __restrict__ pw,
    const float* __restrict__ pb,
    const float* __restrict__ ww,
    const float* __restrict__ wb)
{
    extern __shared__ float sm[];
    float*  sWt   = sm;                       // 4096 floats: sWt[e*64+d] = ww[d][e]
    float4* sWin4 = (float4*)(sm + 4096);     // 2048 float4
    int*    sIdx  = (int*)(sm + 4096 + 8192); // 128
    float*  sPts  = sm + 4096 + 8192 + 128;   // 512 (8 pts x 16 k x 4)
    float*  sWb   = sPts + 512;               // 64
    double* sred  = (double*)(sm + 4096);     // reduction reuses sWin area

    const int tid = threadIdx.x;
    for (int i = tid; i < 64*64; i += 128) {
        int e = i >> 6, d = i & 63;
        sWt[i] = __ldg(ww + d*DIM + e);
    }
    if (tid < 64) sWb[tid] = __ldg(wb + tid);
    __syncthreads();

    const int sub = tid >> 4;     // point slot 0..7
    const int t   = tid & 15;     // d-quad
    const int d0  = 4*t;

    float w[12], br[4], sc1[4], sh1[4];
    #pragma unroll
    for (int j = 0; j < 4; j++) {
        w[j*3+0] = __ldg(pw + (d0+j)*3 + 0);
        w[j*3+1] = __ldg(pw + (d0+j)*3 + 1);
        w[j*3+2] = __ldg(pw + (d0+j)*3 + 2);
        br[j]    = __ldg(pb + d0 + j);
        sc1[j]   = g_stats[d0 + j];
        sh1[j]   = g_stats[64 + d0 + j];
    }
    const float4 bias4 = *(const float4*)&sWb[d0];

    double ds[4] = {0,0,0,0}, dsq[4] = {0,0,0,0};

    for (int g = blockIdx.x; g < NPTS/8; g += gridDim.x) {
        const int n = g*8 + sub;
        __syncthreads();
        sIdx[sub*16 + t] = __ldg(nb + (size_t)n*KNB + t);
        __syncthreads();
        {
            int idx = sIdx[sub*16 + t];
            bool pad = (idx >= NPTS);
            sPts[(sub*16 + t)*4 + 0] = pad ? 1e6f : __ldg(points + (size_t)idx*3    );
            sPts[(sub*16 + t)*4 + 1] = pad ? 1e6f : __ldg(points + (size_t)idx*3 + 1);
            sPts[(sub*16 + t)*4 + 2] = pad ? 1e6f : __ldg(points + (size_t)idx*3 + 2);
        }
        __syncthreads();

        // build win[k][d0..d0+3]
        const float4 q4 = *(const float4*)(g_q + (size_t)n*DIM + d0);
        #pragma unroll
        for (int k = 0; k < KNB; k++) {
            int idx = sIdx[sub*16 + k];
            float x = sPts[(sub*16+k)*4], y = sPts[(sub*16+k)*4+1], z = sPts[(sub*16+k)*4+2];
            float pf0 = fmaxf(fmaf(fmaf(w[2],  z, fmaf(w[1],  y, fmaf(w[0],  x, br[0]))), sc1[0], sh1[0]), 0.f);
            float pf1 = fmaxf(fmaf(fmaf(w[5],  z, fmaf(w[4],  y, fmaf(w[3],  x, br[1]))), sc1[1], sh1[1]), 0.f);
            float pf2 = fmaxf(fmaf(fmaf(w[8],  z, fmaf(w[7],  y, fmaf(w[6],  x, br[2]))), sc1[2], sh1[2]), 0.f);
            float pf3 = fmaxf(fmaf(fmaf(w[11], z, fmaf(w[10], y, fmaf(w[9],  x, br[3]))), sc1[3], sh1[3]), 0.f);
            float4 kg = make_float4(0.f,0.f,0.f,0.f);
            if (idx < NPTS) kg = *(const float4*)(g_k + (size_t)idx*DIM + d0);
            float4 wv;
            wv.x = fmaf(kg.x, q4.x, pf0);
            wv.y = fmaf(kg.y, q4.y, pf1);
            wv.z = fmaf(kg.z, q4.z, pf2);
            wv.w = fmaf(kg.w, q4.w, pf3);
            sWin4[sub*256 + k*16 + t] = wv;
        }
        __syncthreads();

        // GEMM: acc[k] = bias + win[k][:] @ Wt[:, d0..d0+3]
        float4 acc[KNB];
        #pragma unroll
        for (int k = 0; k < KNB; k++) acc[k] = bias4;
        #pragma unroll 4
        for (int e0 = 0; e0 < 64; e0 += 4) {
            float4 w0 = *(const float4*)&sWt[(e0+0)*64 + d0];
            float4 w1 = *(const float4*)&sWt[(e0+1)*64 + d0];
            float4 w2 = *(const float4*)&sWt[(e0+2)*64 + d0];
            float4 w3 = *(const float4*)&sWt[(e0+3)*64 + d0];
            #pragma unroll
            for (int k = 0; k < KNB; k++) {
                float4 a = sWin4[sub*256 + k*16 + (e0 >> 2)];
                acc[k].x = fmaf(a.x, w0.x, fmaf(a.y, w1.x, fmaf(a.z, w2.x, fmaf(a.w, w3.x, acc[k].x))));
                acc[k].y = fmaf(a.x, w0.y, fmaf(a.y, w1.y, fmaf(a.z, w2.y, fmaf(a.w, w3.y, acc[k].y))));
                acc[k].z = fmaf(a.x, w0.z, fmaf(a.y, w1.z, fmaf(a.z, w2.z, fmaf(a.w, w3.z, acc[k].z))));
                acc[k].w = fmaf(a.x, w0.w, fmaf(a.y, w1.w, fmaf(a.z, w2.w, fmaf(a.w, w3.w, acc[k].w))));
            }
        }

        // store w_pre + local stats
        float ls[4] = {0,0,0,0}, lsq[4] = {0,0,0,0};
        #pragma unroll
        for (int k = 0; k < KNB; k++) {
            *(float4*)(g_wpre + ((size_t)n*KNB + k)*DIM + d0) = acc[k];
            ls[0] += acc[k].x; lsq[0] = fmaf(acc[k].x, acc[k].x, lsq[0]);
            ls[1] += acc[k].y; lsq[1] = fmaf(acc[k].y, acc[k].y, lsq[1]);
            ls[2] += acc[k].z; lsq[2] = fmaf(acc[k].z, acc[k].z, lsq[2]);
            ls[3] += acc[k].w; lsq[3] = fmaf(acc[k].w, acc[k].w, lsq[3]);
        }
        #pragma unroll
        for (int j = 0; j < 4; j++) { ds[j] += (double)ls[j]; dsq[j] += (double)lsq[j]; }
    }

    __syncthreads();
    #pragma unroll
    for (int j = 0; j < 4; j++) {
        sred[tid*8 + j]     = ds[j];
        sred[tid*8 + 4 + j] = dsq[j];
    }
    __syncthreads();
    if (tid < 64) {
        int tq = tid >> 2, j = tid & 3;
        double s = 0.0, sq = 0.0;
        #pragma unroll
        for (int sb = 0; sb < 8; sb++) {
            s  += sred[(sb*16 + tq)*8 + j];
            sq += sred[(sb*16 + tq)*8 + 4 + j];
        }
        atomicAdd(&g_acc[128 + tid], s);
        atomicAdd(&g_acc[192 + tid], sq);
    }
}

// ---------------- kernel 6: pass D ----------------
__global__ void __launch_bounds__(128, 4) passD_kernel(
    const float* __restrict__ points,
    const int*   __restrict__ nb,
    const float* __restrict__ pw,
    const float* __restrict__ pb,
    float* __restrict__ out)
{
    __shared__ int   sIdx[8*16];
    __shared__ float sPts[8*16*4];

    const int tid = threadIdx.x;
    const int sub = tid >> 4;
    const int t   = tid & 15;
    const int d0  = 4*t;

    float w[12], br[4], sc1[4], sh1[4], sc2[4], sh2[4];
    #pragma unroll
    for (int j = 0; j < 4; j++) {
        w[j*3+0] = __ldg(pw + (d0+j)*3 + 0);
        w[j*3+1] = __ldg(pw + (d0+j)*3 + 1);
        w[j*3+2] = __ldg(pw + (d0+j)*3 + 2);
        br[j]    = __ldg(pb + d0 + j);
        sc1[j]   = g_stats[d0 + j];
        sh1[j]   = g_stats[64 + d0 + j];
        sc2[j]   = g_stats[128 + d0 + j];
        sh2[j]   = g_stats[192 + d0 + j];
    }

    for (int g = blockIdx.x; g < NPTS/8; g += gridDim.x) {
        const int n = g*8 + sub;
        __syncthreads();
        sIdx[sub*16 + t] = __ldg(nb + (size_t)n*KNB + t);
        __syncthreads();
        {
            int idx = sIdx[sub*16 + t];
            bool pad = (idx >= NPTS);
            sPts[(sub*16 + t)*4 + 0] = pad ? 1e6f : __ldg(points + (size_t)idx*3    );
            sPts[(sub*16 + t)*4 + 1] = pad ? 1e6f : __ldg(points + (size_t)idx*3 + 1);
            sPts[(sub*16 + t)*4 + 2] = pad ? 1e6f : __ldg(points + (size_t)idx*3 + 2);
        }
        __syncthreads();

        float4 wq[KNB];
        #pragma unroll
        for (int k = 0; k < KNB; k++) {
            float4 v = *(const float4*)(g_wpre + ((size_t)n*KNB + k)*DIM + d0);
            wq[k].x = fmaxf(fmaf(v.x, sc2[0], sh2[0]), 0.f);
            wq[k].y = fmaxf(fmaf(v.y, sc2[1], sh2[1]), 0.f);
            wq[k].z = fmaxf(fmaf(v.z, sc2[2], sh2[2]), 0.f);
            wq[k].w = fmaxf(fmaf(v.w, sc2[3], sh2[3]), 0.f);
        }
        float4 mx = wq[0];
        #pragma unroll
        for (int k = 1; k < KNB; k++) {
            mx.x = fmaxf(mx.x, wq[k].x); mx.y = fmaxf(mx.y, wq[k].y);
            mx.z = fmaxf(mx.z, wq[k].z); mx.w = fmaxf(mx.w, wq[k].w);
        }
        float4 se = make_float4(0.f,0.f,0.f,0.f);
        #pragma unroll
        for (int k = 0; k < KNB; k++) {
            wq[k].x = __expf(wq[k].x - mx.x); se.x += wq[k].x;
            wq[k].y = __expf(wq[k].y - mx.y); se.y += wq[k].y;
            wq[k].z = __expf(wq[k].z - mx.z); se.z += wq[k].z;
            wq[k].w = __expf(wq[k].w - mx.w); se.w += wq[k].w;
        }
        float4 inv;
        inv.x = __fdividef(1.f, se.x); inv.y = __fdividef(1.f, se.y);
        inv.z = __fdividef(1.f, se.z); inv.w = __fdividef(1.f, se.w);

        float4 att = make_float4(0.f,0.f,0.f,0.f);
        #pragma unroll
        for (int k = 0; k < KNB; k++) {
            int idx = sIdx[sub*16 + k];
            float x = sPts[(sub*16+k)*4], y = sPts[(sub*16+k)*4+1], z = sPts[(sub*16+k)*4+2];
            float pf0 = fmaxf(fmaf(fmaf(w[2],  z, fmaf(w[1],  y, fmaf(w[0],  x, br[0]))), sc1[0], sh1[0]), 0.f);
            float pf1 = fmaxf(fmaf(fmaf(w[5],  z, fmaf(w[4],  y, fmaf(w[3],  x, br[1]))), sc1[1], sh1[1]), 0.f);
            float pf2 = fmaxf(fmaf(fmaf(w[8],  z, fmaf(w[7],  y, fmaf(w[6],  x, br[2]))), sc1[2], sh1[2]), 0.f);
            float pf3 = fmaxf(fmaf(fmaf(w[11], z, fmaf(w[10], y, fmaf(w[9],  x, br[3]))), sc1[3], sh1[3]), 0.f);
            float4 vg = make_float4(0.f,0.f,0.f,0.f);
            if (idx < NPTS) vg = *(const float4*)(g_v + (size_t)idx*DIM + d0);
            att.x = fmaf(vg.x + pf0, wq[k].x * inv.x, att.x);
            att.y = fmaf(vg.y + pf1, wq[k].y * inv.y, att.y);
            att.z = fmaf(vg.z + pf2, wq[k].z * inv.z, att.z);
            att.w = fmaf(vg.w + pf3, wq[k].w * inv.w, att.w);
        }
        *(float4*)(out + (size_t)n*DIM + d0) = att;
    }
}

// ---------------- launch ----------------
extern "C" void kernel_launch(void* const* d_in, const int* in_sizes, int n_in,
                              void* d_out, int out_size)
{
    const float* points  = (const float*)d_in[0];
    const int*   nbrs    = (const int*)  d_in[1];
    const float* feats   = (const float*)d_in[2];
    const float* q_w = (const float*)d_in[3];  const float* q_b = (const float*)d_in[4];
    const float* k_w = (const float*)d_in[5];  const float* k_b = (const float*)d_in[6];
    const float* v_w = (const float*)d_in[7];  const float* v_b = (const float*)d_in[8];
    const float* p_w = (const float*)d_in[9];  const float* p_b = (const float*)d_in[10];
    const float* p_gamma = (const float*)d_in[11]; const float* p_beta = (const float*)d_in[12];
    const float* w_w = (const float*)d_in[13]; const float* w_b = (const float*)d_in[14];
    const float* w_gamma = (const float*)d_in[15]; const float* w_beta = (const float*)d_in[16];
    float* out = (float*)d_out;

    const int QKV_SMEM  = (12288 + 1280 + 192) * 4;            // 55040 B
    const int PASSC_SMEM = (4096 + 8192 + 128 + 512 + 64) * 4; // 51968 B
    cudaFuncSetAttribute(qkv_kernel,  cudaFuncAttributeMaxDynamicSharedMemorySize, QKV_SMEM);
    cudaFuncSetAttribute(passC_kernel, cudaFuncAttributeMaxDynamicSharedMemorySize, PASSC_SMEM);

    zero_acc_kernel<<<1, 256>>>();
    qkv_kernel<<<592, QKV_THREADS, QKV_SMEM>>>(feats, q_w, q_b, k_w, k_b, v_w, v_b);
    stats1_kernel<<<592, 256>>>(points, nbrs, p_w, p_b);
    finalize_kernel<<<1, 64>>>(p_gamma, p_beta, 0);
    passC_kernel<<<592, 128, PASSC_SMEM>>>(points, nbrs, p_w, p_b, w_w, w_b);
    finalize_kernel<<<1, 64>>>(w_gamma, w_beta, 128);
    passD_kernel<<<1184, 128>>>(points, nbrs, p_w, p_b, out);
}

// round 3
// speedup vs baseline: 2.0005x; 1.0269x over previous
#include <cuda_runtime.h>
#include <math.h>

#define NPTS 100000
#define KNB  16
#define DIM  64
#define NK   (NPTS*KNB)

typedef unsigned long long ull;

// ---------------- f32x2 helpers ----------------
__device__ __forceinline__ ull ffma2(ull a, ull b, ull c) {
    ull d;
    asm("fma.rn.f32x2 %0, %1, %2, %3;" : "=l"(d) : "l"(a), "l"(b), "l"(c));
    return d;
}
__device__ __forceinline__ ull dup2(float x) {
    ull d;
    asm("mov.b64 %0, {%1, %1};" : "=l"(d) : "f"(x));
    return d;
}
__device__ __forceinline__ void unpack2(ull p, float& lo, float& hi) {
    asm("mov.b64 {%0, %1}, %2;" : "=f"(lo), "=f"(hi) : "l"(p));
}

// ---------------- scratch ----------------
__device__ float  g_q[(size_t)NPTS*DIM];
__device__ float  g_k[(size_t)NPTS*DIM];
__device__ float  g_v[(size_t)NPTS*DIM];
__device__ float  g_wpre[(size_t)NPTS*KNB*DIM];   // 409.6 MB
__device__ double g_acc[256];
__device__ float  g_stats[256];

__global__ void zero_acc_kernel() {
    if (threadIdx.x < 256) g_acc[threadIdx.x] = 0.0;
}

// ---------------- frontend: qkv GEMM (blocks < QKV_BLOCKS) + BN1 stats ----------------
#define FE_THREADS   192
#define QKV_BLOCKS   304
#define STATS_BLOCKS 140
#define FE_BLOCKS    (QKV_BLOCKS + STATS_BLOCKS)

__global__ void __launch_bounds__(FE_THREADS) frontend_kernel(
    const float* __restrict__ feats,
    const float* __restrict__ qw, const float* __restrict__ qb,
    const float* __restrict__ kw, const float* __restrict__ kb,
    const float* __restrict__ vw, const float* __restrict__ vb,
    const float* __restrict__ points,
    const int*   __restrict__ nb,
    const float* __restrict__ pw,
    const float* __restrict__ pb)
{
    extern __shared__ float sm[];
    const int tid = threadIdx.x;

    if (blockIdx.x < QKV_BLOCKS) {
        // ---------------- qkv part ----------------
        float* sW    = sm;                  // 12288: sW[e*192 + c] = W_c[c][e]
        float* sFdup = sm + 12288;          // 64*36: sFdup[e*36 + 2p] = (f,f)
        float* sB    = sm + 12288 + 2304;   // 192

        for (int i = tid; i < 192*64; i += FE_THREADS) {
            int c = i % 192, e = i / 192;
            const float* src = (c < 64) ? qw : (c < 128) ? kw : vw;
            sW[e*192 + c] = __ldg(src + (c & 63)*DIM + e);
        }
        if (tid < 192) {
            const float* src = (tid < 64) ? qb : (tid < 128) ? kb : vb;
            sB[tid] = __ldg(src + (tid & 63));
        }
        __syncthreads();

        const int c4 = tid % 48;
        const int pb4 = tid / 48;
        const int c = 4*c4;
        const ull b0 = *(const ull*)&sB[c];
        const ull b1 = *(const ull*)&sB[c+2];
        float* dst = (c < 64) ? g_q : (c < 128) ? g_k : g_v;
        const int cc = c & 63;

        for (int tile = blockIdx.x; tile < NPTS/16; tile += QKV_BLOCKS) {
            const int n0 = tile*16;
            __syncthreads();
            for (int i = tid; i < 16*64; i += FE_THREADS) {
                int e = i & 63, p = i >> 6;
                float f = __ldg(feats + (size_t)(n0+p)*DIM + e);
                *(float2*)&sFdup[e*36 + 2*p] = make_float2(f, f);
            }
            __syncthreads();

            ull acc[4][2];
            #pragma unroll
            for (int p = 0; p < 4; p++) { acc[p][0] = b0; acc[p][1] = b1; }

            #pragma unroll
            for (int e = 0; e < 64; e++) {
                ulonglong2 wv  = *(const ulonglong2*)&sW[e*192 + c];
                ulonglong2 f01 = *(const ulonglong2*)&sFdup[e*36 + 8*pb4];
                ulonglong2 f23 = *(const ulonglong2*)&sFdup[e*36 + 8*pb4 + 4];
                acc[0][0] = ffma2(f01.x, wv.x, acc[0][0]);
                acc[0][1] = ffma2(f01.x, wv.y, acc[0][1]);
                acc[1][0] = ffma2(f01.y, wv.x, acc[1][0]);
                acc[1][1] = ffma2(f01.y, wv.y, acc[1][1]);
                acc[2][0] = ffma2(f23.x, wv.x, acc[2][0]);
                acc[2][1] = ffma2(f23.x, wv.y, acc[2][1]);
                acc[3][0] = ffma2(f23.y, wv.x, acc[3][0]);
                acc[3][1] = ffma2(f23.y, wv.y, acc[3][1]);
            }

            const int nb0 = n0 + 4*pb4;
            #pragma unroll
            for (int p = 0; p < 4; p++) {
                float4 r;
                unpack2(acc[p][0], r.x, r.y);
                unpack2(acc[p][1], r.z, r.w);
                *(float4*)(dst + (size_t)(nb0+p)*DIM + cc) = r;
            }
        }
    } else {
        // ---------------- stats1 part ----------------
        const int quad = tid & 15;
        const int slot = tid >> 4;          // 0..11
        const int d0   = 4*quad;

        float w[12], br[4];
        #pragma unroll
        for (int j = 0; j < 4; j++) {
            w[j*3+0] = __ldg(pw + (d0+j)*3 + 0);
            w[j*3+1] = __ldg(pw + (d0+j)*3 + 1);
            w[j*3+2] = __ldg(pw + (d0+j)*3 + 2);
            br[j]    = __ldg(pb + d0 + j);
        }

        float s[4] = {0,0,0,0}, sq[4] = {0,0,0,0};
        const int bid = blockIdx.x - QKV_BLOCKS;
        for (int r = bid*12 + slot; r < NK; r += STATS_BLOCKS*12) {
            int idx = __ldg(nb + r);
            float x, y, z;
            if (idx >= NPTS) { x = y = z = 1e6f; }
            else {
                x = __ldg(points + (size_t)idx*3    );
                y = __ldg(points + (size_t)idx*3 + 1);
                z = __ldg(points + (size_t)idx*3 + 2);
            }
            #pragma unroll
            for (int j = 0; j < 4; j++) {
                float v = fmaf(w[j*3+2], z, fmaf(w[j*3+1], y, fmaf(w[j*3+0], x, br[j])));
                s[j] += v;
                sq[j] = fmaf(v, v, sq[j]);
            }
        }

        float* sred = sm;   // 192*8 floats
        #pragma unroll
        for (int j = 0; j < 4; j++) {
            sred[tid*8 + j]     = s[j];
            sred[tid*8 + 4 + j] = sq[j];
        }
        __syncthreads();
        if (tid < 64) {
            int tq = tid >> 2, j = tid & 3;
            double ds = 0.0, dsq = 0.0;
            #pragma unroll
            for (int sl = 0; sl < 12; sl++) {
                ds  += (double)sred[(sl*16 + tq)*8 + j];
                dsq += (double)sred[(sl*16 + tq)*8 + 4 + j];
            }
            atomicAdd(&g_acc[tid],      ds);
            atomicAdd(&g_acc[64 + tid], dsq);
        }
    }
}

// ---------------- finalize ----------------
__global__ void finalize_kernel(const float* __restrict__ gamma,
                                const float* __restrict__ beta, int base)
{
    int d = threadIdx.x;
    if (d < 64) {
        double cnt = (double)NK;
        double m   = g_acc[base + d] / cnt;
        double var = g_acc[base + 64 + d] / cnt - m*m;
        double rs  = 1.0 / sqrt(var + 1e-5);
        double g   = (double)__ldg(gamma + d);
        g_stats[base + d]      = (float)(rs * g);
        g_stats[base + 64 + d] = (float)((double)__ldg(beta + d) - m * rs * g);
    }
}

// ---------------- pass C: gather + win build + f32x2 GEMM + w_pre store + BN2 stats ----
// smem: sWtDup[64e][128] (dup'd W^T, 32KB) + sWin[8 subs][64e][16k + pad] + sPts + sIdx
#define PASSC_BLOCKS 444
__global__ void __launch_bounds__(128, 3) passC_kernel(
    const float* __restrict__ points,
    const int*   __restrict__ nb,
    const float* __restrict__ pw,
    const float* __restrict__ pb,
    const float* __restrict__ ww,
    const float* __restrict__ wb)
{
    extern __shared__ float sm[];
    float* sWtDup = sm;                        // 8192 floats
    float* sWin   = sm + 8192;                 // 8320 floats (8 * 1040)
    float* sPts   = sm + 8192 + 8320;          // 512
    int*   sIdx   = (int*)(sm + 8192 + 8320 + 512); // 128

    const int tid = threadIdx.x;
    for (int i = tid; i < 4096; i += 128) {
        int d = i & 63, e = i >> 6;
        float v = __ldg(ww + d*DIM + e);
        *(float2*)&sWtDup[e*128 + 2*d] = make_float2(v, v);
    }
    __syncthreads();

    const int sub = tid >> 4;
    const int t   = tid & 15;
    const int d0  = 4*t;
    const int sw  = 2*(t & 7);     // write swizzle (even)

    float w[12], br[4], sc1[4], sh1[4];
    #pragma unroll
    for (int j = 0; j < 4; j++) {
        w[j*3+0] = __ldg(pw + (d0+j)*3 + 0);
        w[j*3+1] = __ldg(pw + (d0+j)*3 + 1);
        w[j*3+2] = __ldg(pw + (d0+j)*3 + 2);
        br[j]    = __ldg(pb + d0 + j);
        sc1[j]   = g_stats[d0 + j];
        sh1[j]   = g_stats[64 + d0 + j];
    }
    const float4 bv = *(const float4*)(wb + d0);
    ull bp[4];
    bp[0] = dup2(bv.x); bp[1] = dup2(bv.y); bp[2] = dup2(bv.z); bp[3] = dup2(bv.w);

    double ds[4] = {0,0,0,0}, dsq[4] = {0,0,0,0};
    float* winb = &sWin[sub*1040];

    for (int g = blockIdx.x; g < NPTS/8; g += PASSC_BLOCKS) {
        const int n = g*8 + sub;
        __syncthreads();
        sIdx[sub*16 + t] = __ldg(nb + (size_t)n*KNB + t);
        __syncthreads();
        {
            int idx = sIdx[sub*16 + t];
            bool pad = (idx >= NPTS);
            sPts[(sub*16 + t)*4 + 0] = pad ? 1e6f : __ldg(points + (size_t)idx*3    );
            sPts[(sub*16 + t)*4 + 1] = pad ? 1e6f : __ldg(points + (size_t)idx*3 + 1);
            sPts[(sub*16 + t)*4 + 2] = pad ? 1e6f : __ldg(points + (size_t)idx*3 + 2);
        }
        __syncthreads();

        // win build: rows e=d0+j, cols (2kp)^sw .. +1 hold k=2kp,2kp+1
        const float4 q4 = *(const float4*)(g_q + (size_t)n*DIM + d0);
        #pragma unroll
        for (int kp = 0; kp < 8; kp++) {
            int k0 = 2*kp, k1 = 2*kp + 1;
            int i0 = sIdx[sub*16 + k0], i1 = sIdx[sub*16 + k1];
            float x0 = sPts[(sub*16+k0)*4], y0 = sPts[(sub*16+k0)*4+1], z0 = sPts[(sub*16+k0)*4+2];
            float x1 = sPts[(sub*16+k1)*4], y1 = sPts[(sub*16+k1)*4+1], z1 = sPts[(sub*16+k1)*4+2];
            float4 kg0 = make_float4(0.f,0.f,0.f,0.f), kg1 = kg0;
            if (i0 < NPTS) kg0 = *(const float4*)(g_k + (size_t)i0*DIM + d0);
            if (i1 < NPTS) kg1 = *(const float4*)(g_k + (size_t)i1*DIM + d0);
            const int col = (2*kp) ^ sw;
            #pragma unroll
            for (int j = 0; j < 4; j++) {
                float pl0 = fmaf(w[j*3+2], z0, fmaf(w[j*3+1], y0, fmaf(w[j*3+0], x0, br[j])));
                float pl1 = fmaf(w[j*3+2], z1, fmaf(w[j*3+1], y1, fmaf(w[j*3+0], x1, br[j])));
                float pf0 = fmaxf(fmaf(pl0, sc1[j], sh1[j]), 0.f);
                float pf1 = fmaxf(fmaf(pl1, sc1[j], sh1[j]), 0.f);
                float kgj0 = (j==0)?kg0.x:(j==1)?kg0.y:(j==2)?kg0.z:kg0.w;
                float kgj1 = (j==0)?kg1.x:(j==1)?kg1.y:(j==2)?kg1.z:kg1.w;
                float qj   = (j==0)?q4.x:(j==1)?q4.y:(j==2)?q4.z:q4.w;
                *(float2*)&winb[(d0+j)*16 + col] =
                    make_float2(fmaf(kgj0, qj, pf0), fmaf(kgj1, qj, pf1));
            }
        }
        __syncthreads();

        // GEMM: acc[kp][j] (pack = (k=2kp, k=2kp+1) at channel d0+j)
        ull acc[8][4];
        #pragma unroll
        for (int kp = 0; kp < 8; kp++)
            #pragma unroll
            for (int j = 0; j < 4; j++) acc[kp][j] = bp[j];

        for (int eo = 0; eo < 2; eo++) {
            const float* wrow = winb + eo*32*16;
            const float* drow = sWtDup + eo*32*128 + 8*t;
            #pragma unroll
            for (int eu = 0; eu < 32; eu++) {
                const int h = (eu >> 2) & 7;     // read rotation (compile-time)
                ulonglong2 A0 = *(const ulonglong2*)&wrow[eu*16 + 0];
                ulonglong2 A1 = *(const ulonglong2*)&wrow[eu*16 + 4];
                ulonglong2 A2 = *(const ulonglong2*)&wrow[eu*16 + 8];
                ulonglong2 A3 = *(const ulonglong2*)&wrow[eu*16 + 12];
                ulonglong2 W0 = *(const ulonglong2*)&drow[eu*128];      // (d0,d0),(d1,d1)
                ulonglong2 W1 = *(const ulonglong2*)&drow[eu*128 + 4];  // (d2,d2),(d3,d3)
                #define C_STEP(m, av)                                   \
                {   const int kp = (m) ^ h;                             \
                    acc[kp][0] = ffma2(av, W0.x, acc[kp][0]);           \
                    acc[kp][1] = ffma2(av, W0.y, acc[kp][1]);           \
                    acc[kp][2] = ffma2(av, W1.x, acc[kp][2]);           \
                    acc[kp][3] = ffma2(av, W1.y, acc[kp][3]); }
                C_STEP(0, A0.x) C_STEP(1, A0.y)
                C_STEP(2, A1.x) C_STEP(3, A1.y)
                C_STEP(4, A2.x) C_STEP(5, A2.y)
                C_STEP(6, A3.x) C_STEP(7, A3.y)
                #undef C_STEP
            }
        }

        // unpack, store w_pre, accumulate BN2 stats
        float ls[4] = {0,0,0,0}, lsq[4] = {0,0,0,0};
        #pragma unroll
        for (int kp = 0; kp < 8; kp++) {
            float4 r0, r1;
            unpack2(acc[kp][0], r0.x, r1.x);
            unpack2(acc[kp][1], r0.y, r1.y);
            unpack2(acc[kp][2], r0.z, r1.z);
            unpack2(acc[kp][3], r0.w, r1.w);
            *(float4*)(g_wpre + ((size_t)n*KNB + 2*kp    )*DIM + d0) = r0;
            *(float4*)(g_wpre + ((size_t)n*KNB + 2*kp + 1)*DIM + d0) = r1;
            ls[0] += r0.x + r1.x;  lsq[0] = fmaf(r0.x, r0.x, fmaf(r1.x, r1.x, lsq[0]));
            ls[1] += r0.y + r1.y;  lsq[1] = fmaf(r0.y, r0.y, fmaf(r1.y, r1.y, lsq[1]));
            ls[2] += r0.z + r1.z;  lsq[2] = fmaf(r0.z, r0.z, fmaf(r1.z, r1.z, lsq[2]));
            ls[3] += r0.w + r1.w;  lsq[3] = fmaf(r0.w, r0.w, fmaf(r1.w, r1.w, lsq[3]));
        }
        #pragma unroll
        for (int j = 0; j < 4; j++) { ds[j] += (double)ls[j]; dsq[j] += (double)lsq[j]; }
    }

    // block reduction (reuse smem)
    __syncthreads();
    double* sred = (double*)sm;
    #pragma unroll
    for (int j = 0; j < 4; j++) {
        sred[tid*8 + j]     = ds[j];
        sred[tid*8 + 4 + j] = dsq[j];
    }
    __syncthreads();
    if (tid < 64) {
        int tq = tid >> 2, j = tid & 3;
        double s = 0.0, sq = 0.0;
        #pragma unroll
        for (int sb = 0; sb < 8; sb++) {
            s  += sred[(sb*16 + tq)*8 + j];
            sq += sred[(sb*16 + tq)*8 + 4 + j];
        }
        atomicAdd(&g_acc[128 + tid], s);
        atomicAdd(&g_acc[192 + tid], sq);
    }
}

// ---------------- pass D ----------------
__global__ void __launch_bounds__(128, 4) passD_kernel(
    const float* __restrict__ points,
    const int*   __restrict__ nb,
    const float* __restrict__ pw,
    const float* __restrict__ pb,
    float* __restrict__ out)
{
    __shared__ int   sIdx[8*16];
    __shared__ float sPts[8*16*4];

    const int tid = threadIdx.x;
    const int sub = tid >> 4;
    const int t   = tid & 15;
    const int d0  = 4*t;

    float w[12], br[4], sc1[4], sh1[4], sc2[4], sh2[4];
    #pragma unroll
    for (int j = 0; j < 4; j++) {
        w[j*3+0] = __ldg(pw + (d0+j)*3 + 0);
        w[j*3+1] = __ldg(pw + (d0+j)*3 + 1);
        w[j*3+2] = __ldg(pw + (d0+j)*3 + 2);
        br[j]    = __ldg(pb + d0 + j);
        sc1[j]   = g_stats[d0 + j];
        sh1[j]   = g_stats[64 + d0 + j];
        sc2[j]   = g_stats[128 + d0 + j];
        sh2[j]   = g_stats[192 + d0 + j];
    }

    for (int g = blockIdx.x; g < NPTS/8; g += gridDim.x) {
        const int n = g*8 + sub;
        __syncthreads();
        sIdx[sub*16 + t] = __ldg(nb + (size_t)n*KNB + t);
        __syncthreads();
        {
            int idx = sIdx[sub*16 + t];
            bool pad = (idx >= NPTS);
            sPts[(sub*16 + t)*4 + 0] = pad ? 1e6f : __ldg(points + (size_t)idx*3    );
            sPts[(sub*16 + t)*4 + 1] = pad ? 1e6f : __ldg(points + (size_t)idx*3 + 1);
            sPts[(sub*16 + t)*4 + 2] = pad ? 1e6f : __ldg(points + (size_t)idx*3 + 2);
        }
        __syncthreads();

        float4 wq[KNB];
        #pragma unroll
        for (int k = 0; k < KNB; k++) {
            float4 v = *(const float4*)(g_wpre + ((size_t)n*KNB + k)*DIM + d0);
            wq[k].x = fmaxf(fmaf(v.x, sc2[0], sh2[0]), 0.f);
            wq[k].y = fmaxf(fmaf(v.y, sc2[1], sh2[1]), 0.f);
            wq[k].z = fmaxf(fmaf(v.z, sc2[2], sh2[2]), 0.f);
            wq[k].w = fmaxf(fmaf(v.w, sc2[3], sh2[3]), 0.f);
        }
        float4 mx = wq[0];
        #pragma unroll
        for (int k = 1; k < KNB; k++) {
            mx.x = fmaxf(mx.x, wq[k].x); mx.y = fmaxf(mx.y, wq[k].y);
            mx.z = fmaxf(mx.z, wq[k].z); mx.w = fmaxf(mx.w, wq[k].w);
        }
        float4 se = make_float4(0.f,0.f,0.f,0.f);
        #pragma unroll
        for (int k = 0; k < KNB; k++) {
            wq[k].x = __expf(wq[k].x - mx.x); se.x += wq[k].x;
            wq[k].y = __expf(wq[k].y - mx.y); se.y += wq[k].y;
            wq[k].z = __expf(wq[k].z - mx.z); se.z += wq[k].z;
            wq[k].w = __expf(wq[k].w - mx.w); se.w += wq[k].w;
        }
        float4 inv;
        inv.x = __fdividef(1.f, se.x); inv.y = __fdividef(1.f, se.y);
        inv.z = __fdividef(1.f, se.z); inv.w = __fdividef(1.f, se.w);

        float4 att = make_float4(0.f,0.f,0.f,0.f);
        #pragma unroll
        for (int k = 0; k < KNB; k++) {
            int idx = sIdx[sub*16 + k];
            float x = sPts[(sub*16+k)*4], y = sPts[(sub*16+k)*4+1], z = sPts[(sub*16+k)*4+2];
            float pf0 = fmaxf(fmaf(fmaf(w[2],  z, fmaf(w[1],  y, fmaf(w[0],  x, br[0]))), sc1[0], sh1[0]), 0.f);
            float pf1 = fmaxf(fmaf(fmaf(w[5],  z, fmaf(w[4],  y, fmaf(w[3],  x, br[1]))), sc1[1], sh1[1]), 0.f);
            float pf2 = fmaxf(fmaf(fmaf(w[8],  z, fmaf(w[7],  y, fmaf(w[6],  x, br[2]))), sc1[2], sh1[2]), 0.f);
            float pf3 = fmaxf(fmaf(fmaf(w[11], z, fmaf(w[10], y, fmaf(w[9],  x, br[3]))), sc1[3], sh1[3]), 0.f);
            float4 vg = make_float4(0.f,0.f,0.f,0.f);
            if (idx < NPTS) vg = *(const float4*)(g_v + (size_t)idx*DIM + d0);
            att.x = fmaf(vg.x + pf0, wq[k].x * inv.x, att.x);
            att.y = fmaf(vg.y + pf1, wq[k].y * inv.y, att.y);
            att.z = fmaf(vg.z + pf2, wq[k].z * inv.z, att.z);
            att.w = fmaf(vg.w + pf3, wq[k].w * inv.w, att.w);
        }
        *(float4*)(out + (size_t)n*DIM + d0) = att;
    }
}

// ---------------- launch ----------------
extern "C" void kernel_launch(void* const* d_in, const int* in_sizes, int n_in,
                              void* d_out, int out_size)
{
    const float* points  = (const float*)d_in[0];
    const int*   nbrs    = (const int*)  d_in[1];
    const float* feats   = (const float*)d_in[2];
    const float* q_w = (const float*)d_in[3];  const float* q_b = (const float*)d_in[4];
    const float* k_w = (const float*)d_in[5];  const float* k_b = (const float*)d_in[6];
    const float* v_w = (const float*)d_in[7];  const float* v_b = (const float*)d_in[8];
    const float* p_w = (const float*)d_in[9];  const float* p_b = (const float*)d_in[10];
    const float* p_gamma = (const float*)d_in[11]; const float* p_beta = (const float*)d_in[12];
    const float* w_w = (const float*)d_in[13]; const float* w_b = (const float*)d_in[14];
    const float* w_gamma = (const float*)d_in[15]; const float* w_beta = (const float*)d_in[16];
    float* out = (float*)d_out;

    const int FE_SMEM    = (12288 + 2304 + 192) * 4;           // 59136 B
    const int PASSC_SMEM = (8192 + 8320 + 512 + 128) * 4;      // 68608 B
    cudaFuncSetAttribute(frontend_kernel, cudaFuncAttributeMaxDynamicSharedMemorySize, FE_SMEM);
    cudaFuncSetAttribute(passC_kernel,    cudaFuncAttributeMaxDynamicSharedMemorySize, PASSC_SMEM);

    zero_acc_kernel<<<1, 256>>>();
    frontend_kernel<<<FE_BLOCKS, FE_THREADS, FE_SMEM>>>(
        feats, q_w, q_b, k_w, k_b, v_w, v_b, points, nbrs, p_w, p_b);
    finalize_kernel<<<1, 64>>>(p_gamma, p_beta, 0);
    passC_kernel<<<PASSC_BLOCKS, 128, PASSC_SMEM>>>(points, nbrs, p_w, p_b, w_w, w_b);
    finalize_kernel<<<1, 64>>>(w_gamma, w_beta, 128);
    passD_kernel<<<1184, 128>>>(points, nbrs, p_w, p_b, out);
}

// round 5
// speedup vs baseline: 2.2633x; 1.1314x over previous
#include <cuda_runtime.h>
#include <cuda_bf16.h>
#include <math.h>
#include <stdint.h>

#define NPTS 100000
#define KNB  16
#define DIM  64
#define NK   (NPTS*KNB)

typedef unsigned long long ull;

// ---------------- f32x2 helpers (frontend) ----------------
__device__ __forceinline__ ull ffma2(ull a, ull b, ull c) {
    ull d;
    asm("fma.rn.f32x2 %0, %1, %2, %3;" : "=l"(d) : "l"(a), "l"(b), "l"(c));
    return d;
}
__device__ __forceinline__ void unpack2(ull p, float& lo, float& hi) {
    asm("mov.b64 {%0, %1}, %2;" : "=f"(lo), "=f"(hi) : "l"(p));
}

// ---------------- mma helpers ----------------
__device__ __forceinline__ uint32_t smem_u32(const void* p) {
    uint32_t a;
    asm("{ .reg .u64 t; cvta.to.shared.u64 t, %1; cvt.u32.u64 %0, t; }" : "=r"(a) : "l"(p));
    return a;
}
__device__ __forceinline__ void ldsm_x4(uint32_t* r, uint32_t addr) {
    asm volatile("ldmatrix.sync.aligned.m8n8.x4.shared.b16 {%0,%1,%2,%3}, [%4];"
        : "=r"(r[0]), "=r"(r[1]), "=r"(r[2]), "=r"(r[3]) : "r"(addr));
}
__device__ __forceinline__ void mma16816(float* d, const uint32_t* a, const uint32_t* b) {
    asm volatile("mma.sync.aligned.m16n8k16.row.col.f32.bf16.bf16.f32 "
        "{%0,%1,%2,%3}, {%4,%5,%6,%7}, {%8,%9}, {%0,%1,%2,%3};"
        : "+f"(d[0]), "+f"(d[1]), "+f"(d[2]), "+f"(d[3])
        : "r"(a[0]), "r"(a[1]), "r"(a[2]), "r"(a[3]), "r"(b[0]), "r"(b[1]));
}
#define SWZ(o) ((o) ^ (((o) >> 3) & 0x70))

// ---------------- scratch ----------------
__device__ float  g_q[(size_t)NPTS*DIM];
__device__ float  g_k[(size_t)NPTS*DIM];
__device__ float  g_v[(size_t)NPTS*DIM];
__device__ float  g_wpre[(size_t)NPTS*KNB*DIM];
__device__ double g_acc[256];
__device__ float  g_stats[256];

__global__ void zero_acc_kernel() {
    if (threadIdx.x < 256) g_acc[threadIdx.x] = 0.0;
}

// ---------------- frontend: qkv GEMM + BN1 stats ----------------
#define FE_THREADS   192
#define QKV_BLOCKS   304
#define STATS_BLOCKS 140
#define FE_BLOCKS    (QKV_BLOCKS + STATS_BLOCKS)

__global__ void __launch_bounds__(FE_THREADS) frontend_kernel(
    const float* __restrict__ feats,
    const float* __restrict__ qw, const float* __restrict__ qb,
    const float* __restrict__ kw, const float* __restrict__ kb,
    const float* __restrict__ vw, const float* __restrict__ vb,
    const float* __restrict__ points,
    const int*   __restrict__ nb,
    const float* __restrict__ pw,
    const float* __restrict__ pb)
{
    extern __shared__ float sm[];
    const int tid = threadIdx.x;

    if (blockIdx.x < QKV_BLOCKS) {
        float* sW    = sm;
        float* sFdup = sm + 12288;
        float* sB    = sm + 12288 + 2304;

        for (int i = tid; i < 192*64; i += FE_THREADS) {
            int c = i % 192, e = i / 192;
            const float* src = (c < 64) ? qw : (c < 128) ? kw : vw;
            sW[e*192 + c] = __ldg(src + (c & 63)*DIM + e);
        }
        if (tid < 192) {
            const float* src = (tid < 64) ? qb : (tid < 128) ? kb : vb;
            sB[tid] = __ldg(src + (tid & 63));
        }
        __syncthreads();

        const int c4 = tid % 48;
        const int pb4 = tid / 48;
        const int c = 4*c4;
        const ull b0 = *(const ull*)&sB[c];
        const ull b1 = *(const ull*)&sB[c+2];
        float* dst = (c < 64) ? g_q : (c < 128) ? g_k : g_v;
        const int cc = c & 63;

        for (int tile = blockIdx.x; tile < NPTS/16; tile += QKV_BLOCKS) {
            const int n0 = tile*16;
            __syncthreads();
            for (int i = tid; i < 16*64; i += FE_THREADS) {
                int e = i & 63, p = i >> 6;
                float f = __ldg(feats + (size_t)(n0+p)*DIM + e);
                *(float2*)&sFdup[e*36 + 2*p] = make_float2(f, f);
            }
            __syncthreads();

            ull acc[4][2];
            #pragma unroll
            for (int p = 0; p < 4; p++) { acc[p][0] = b0; acc[p][1] = b1; }

            #pragma unroll
            for (int e = 0; e < 64; e++) {
                ulonglong2 wv  = *(const ulonglong2*)&sW[e*192 + c];
                ulonglong2 f01 = *(const ulonglong2*)&sFdup[e*36 + 8*pb4];
                ulonglong2 f23 = *(const ulonglong2*)&sFdup[e*36 + 8*pb4 + 4];
                acc[0][0] = ffma2(f01.x, wv.x, acc[0][0]);
                acc[0][1] = ffma2(f01.x, wv.y, acc[0][1]);
                acc[1][0] = ffma2(f01.y, wv.x, acc[1][0]);
                acc[1][1] = ffma2(f01.y, wv.y, acc[1][1]);
                acc[2][0] = ffma2(f23.x, wv.x, acc[2][0]);
                acc[2][1] = ffma2(f23.x, wv.y, acc[2][1]);
                acc[3][0] = ffma2(f23.y, wv.x, acc[3][0]);
                acc[3][1] = ffma2(f23.y, wv.y, acc[3][1]);
            }

            const int nb0 = n0 + 4*pb4;
            #pragma unroll
            for (int p = 0; p < 4; p++) {
                float4 r;
                unpack2(acc[p][0], r.x, r.y);
                unpack2(acc[p][1], r.z, r.w);
                *(float4*)(dst + (size_t)(nb0+p)*DIM + cc) = r;
            }
        }
    } else {
        const int quad = tid & 15;
        const int slot = tid >> 4;
        const int d0   = 4*quad;

        float w[12], br[4];
        #pragma unroll
        for (int j = 0; j < 4; j++) {
            w[j*3+0] = __ldg(pw + (d0+j)*3 + 0);
            w[j*3+1] = __ldg(pw + (d0+j)*3 + 1);
            w[j*3+2] = __ldg(pw + (d0+j)*3 + 2);
            br[j]    = __ldg(pb + d0 + j);
        }

        float s[4] = {0,0,0,0}, sq[4] = {0,0,0,0};
        const int bid = blockIdx.x - QKV_BLOCKS;
        for (int r = bid*12 + slot; r < NK; r += STATS_BLOCKS*12) {
            int idx = __ldg(nb + r);
            float x, y, z;
            if (idx >= NPTS) { x = y = z = 1e6f; }
            else {
                x = __ldg(points + (size_t)idx*3    );
                y = __ldg(points + (size_t)idx*3 + 1);
                z = __ldg(points + (size_t)idx*3 + 2);
            }
            #pragma unroll
            for (int j = 0; j < 4; j++) {
                float v = fmaf(w[j*3+2], z, fmaf(w[j*3+1], y, fmaf(w[j*3+0], x, br[j])));
                s[j] += v;
                sq[j] = fmaf(v, v, sq[j]);
            }
        }

        float* sred = sm;
        #pragma unroll
        for (int j = 0; j < 4; j++) {
            sred[tid*8 + j]     = s[j];
            sred[tid*8 + 4 + j] = sq[j];
        }
        __syncthreads();
        if (tid < 64) {
            int tq = tid >> 2, j = tid & 3;
            double ds = 0.0, dsq = 0.0;
            #pragma unroll
            for (int sl = 0; sl < 12; sl++) {
                ds  += (double)sred[(sl*16 + tq)*8 + j];
                dsq += (double)sred[(sl*16 + tq)*8 + 4 + j];
            }
            atomicAdd(&g_acc[tid],      ds);
            atomicAdd(&g_acc[64 + tid], dsq);
        }
    }
}

// ---------------- finalize ----------------
__global__ void finalize_kernel(const float* __restrict__ gamma,
                                const float* __restrict__ beta, int base)
{
    int d = threadIdx.x;
    if (d < 64) {
        double cnt = (double)NK;
        double m   = g_acc[base + d] / cnt;
        double var = g_acc[base + 64 + d] / cnt - m*m;
        double rs  = 1.0 / sqrt(var + 1e-5);
        double g   = (double)__ldg(gamma + d);
        g_stats[base + d]      = (float)(rs * g);
        g_stats[base + 64 + d] = (float)((double)__ldg(beta + d) - m * rs * g);
    }
}

// ---------------- pass C: mma.sync bf16 2-term split GEMM ----------------
#define OFF_BHI  0
#define OFF_BLO  8192
#define OFF_AHI  16384
#define OFF_ALO  32768
#define OFF_Q    49152
#define OFF_C    51200
#define OFF_WB   52224
#define PC_SMEM  52480
#define PC_BLOCKS 296

__global__ void __launch_bounds__(128) passC_kernel(
    const float* __restrict__ points,
    const int*   __restrict__ nb,
    const float* __restrict__ pw,
    const float* __restrict__ pb,
    const float* __restrict__ ww,
    const float* __restrict__ wb)
{
    extern __shared__ __align__(1024) char smc[];
    const uint32_t sb = smem_u32(smc);
    const int tid  = threadIdx.x;
    const int wid  = tid >> 5;
    const int lane = tid & 31;

    float* sQ  = (float*)(smc + OFF_Q);
    float* sC  = (float*)(smc + OFF_C);
    float* sWb = (float*)(smc + OFF_WB);

    // build B tiles (bf16 hi/lo of ww, SW128, [64 d rows x 64 e], row=128B)
    for (int i = tid; i < 4096; i += 128) {
        int d = i >> 6, e = i & 63;
        float v = __ldg(ww + d*DIM + e);
        __nv_bfloat16 h = __float2bfloat16(v);
        float lo = v - __bfloat162float(h);
        uint32_t sw = SWZ((uint32_t)(d*128 + e*2));
        *(__nv_bfloat16*)(smc + OFF_BHI + sw) = h;
        *(__nv_bfloat16*)(smc + OFF_BLO + sw) = __float2bfloat16(lo);
    }
    if (tid < 64) {
        float sc = g_stats[tid], sh = g_stats[64 + tid];
        sC[0*64 + tid] = sc * __ldg(pw + tid*3    );
        sC[1*64 + tid] = sc * __ldg(pw + tid*3 + 1);
        sC[2*64 + tid] = sc * __ldg(pw + tid*3 + 2);
        sC[3*64 + tid] = fmaf(sc, __ldg(pb + tid), sh);
        sWb[tid] = __ldg(wb + tid);
    }
    __syncthreads();

    const int m  = tid;          // A row 0..127
    const int p  = m >> 4;       // point slot
    const int kk = m & 15;       // neighbor index

    // stats accumulators: cols nt*8 + 2*(lane&3) + {0,1}
    float2 s[8], q2[8];
    #pragma unroll
    for (int nt = 0; nt < 8; nt++) { s[nt] = make_float2(0.f,0.f); q2[nt] = make_float2(0.f,0.f); }

    const int c4 = 2*(lane & 3);
    const int rb = wid*32 + (lane >> 2);

    for (int tile = blockIdx.x; tile < NPTS/8; tile += PC_BLOCKS) {
        __syncthreads();   // prev iter's ldmatrix reads done; sQ reuse

        // stage q rows
        {
            int pp = tid >> 4, e4 = (tid & 15) * 4;
            *(float4*)&sQ[pp*64 + e4] =
                *(const float4*)(g_q + (size_t)(tile*8 + pp)*DIM + e4);
        }
        __syncwarp();

        const int n = tile*8 + p;
        int idx = __ldg(nb + (size_t)n*KNB + kk);
        bool pad = (idx >= NPTS);
        float x, y, z;
        if (pad) { x = y = z = 1e6f; }
        else {
            x = __ldg(points + (size_t)idx*3    );
            y = __ldg(points + (size_t)idx*3 + 1);
            z = __ldg(points + (size_t)idx*3 + 2);
        }
        const float* krow = g_k + (size_t)(pad ? 0 : idx)*DIM;

        // build A row m (hi/lo bf16, SW128)
        #pragma unroll
        for (int e0 = 0; e0 < 64; e0 += 4) {
            float4 kg = pad ? make_float4(0.f,0.f,0.f,0.f) : *(const float4*)(krow + e0);
            float4 q4 = *(const float4*)&sQ[p*64 + e0];
            float4 cx = *(const float4*)&sC[0*64 + e0];
            float4 cy = *(const float4*)&sC[1*64 + e0];
            float4 cz = *(const float4*)&sC[2*64 + e0];
            float4 cb = *(const float4*)&sC[3*64 + e0];

            float win[4];
            win[0] = fmaf(kg.x, q4.x, fmaxf(fmaf(cz.x, z, fmaf(cy.x, y, fmaf(cx.x, x, cb.x))), 0.f));
            win[1] = fmaf(kg.y, q4.y, fmaxf(fmaf(cz.y, z, fmaf(cy.y, y, fmaf(cx.y, x, cb.y))), 0.f));
            win[2] = fmaf(kg.z, q4.z, fmaxf(fmaf(cz.z, z, fmaf(cy.z, y, fmaf(cx.z, x, cb.z))), 0.f));
            win[3] = fmaf(kg.w, q4.w, fmaxf(fmaf(cz.w, z, fmaf(cy.w, y, fmaf(cx.w, x, cb.w))), 0.f));

            __nv_bfloat16 h[4]; float lo[4];
            #pragma unroll
            for (int j = 0; j < 4; j++) {
                h[j]  = __float2bfloat16(win[j]);
                lo[j] = win[j] - __bfloat162float(h[j]);
            }
            uint32_t sw = SWZ((uint32_t)(m*128 + e0*2));
            __nv_bfloat162 h01 = __halves2bfloat162(h[0], h[1]);
            __nv_bfloat162 h23 = __halves2bfloat162(h[2], h[3]);
            *(uint2*)(smc + OFF_AHI + sw) = make_uint2(*(uint32_t*)&h01, *(uint32_t*)&h23);
            __nv_bfloat162 l01 = __floats2bfloat162_rn(lo[0], lo[1]);
            __nv_bfloat162 l23 = __floats2bfloat162_rn(lo[2], lo[3]);
            *(uint2*)(smc + OFF_ALO + sw) = make_uint2(*(uint32_t*)&l01, *(uint32_t*)&l23);
        }
        __syncthreads();

        // ---- warp-level GEMM: rows [wid*32, wid*32+32), all 64 cols ----
        float acc[2][8][4];
        #pragma unroll
        for (int mt = 0; mt < 2; mt++)
            #pragma unroll
            for (int nt = 0; nt < 8; nt++)
                #pragma unroll
                for (int r = 0; r < 4; r++) acc[mt][nt][r] = 0.f;

        #pragma unroll
        for (int ks = 0; ks < 4; ks++) {
            uint32_t ah[2][4], al[2][4];
            #pragma unroll
            for (int mt = 0; mt < 2; mt++) {
                uint32_t off = SWZ((uint32_t)((wid*32 + mt*16 + (lane & 15))*128
                                              + ks*32 + ((lane >> 4) << 4)));
                ldsm_x4(ah[mt], sb + OFF_AHI + off);
                ldsm_x4(al[mt], sb + OFF_ALO + off);
            }
            uint32_t bh[4][4], bl[4][4];
            #pragma unroll
            for (int np = 0; np < 4; np++) {
                int nrow = np*16 + (lane & 7) + ((lane >> 4) << 3);
                uint32_t off = SWZ((uint32_t)(nrow*128 + ks*32 + (((lane >> 3) & 1) << 4)));
                ldsm_x4(bh[np], sb + OFF_BHI + off);
                ldsm_x4(bl[np], sb + OFF_BLO + off);
            }
            #pragma unroll
            for (int mt = 0; mt < 2; mt++)
                #pragma unroll
                for (int np = 0; np < 4; np++) {
                    mma16816(acc[mt][2*np  ], ah[mt], &bh[np][0]);
                    mma16816(acc[mt][2*np  ], al[mt], &bh[np][0]);
                    mma16816(acc[mt][2*np  ], ah[mt], &bl[np][0]);
                    mma16816(acc[mt][2*np+1], ah[mt], &bh[np][2]);
                    mma16816(acc[mt][2*np+1], al[mt], &bh[np][2]);
                    mma16816(acc[mt][2*np+1], ah[mt], &bl[np][2]);
                }
        }

        // ---- epilogue: bias, store, stats ----
        #pragma unroll
        for (int nt = 0; nt < 8; nt++) {
            float bx = sWb[nt*8 + c4];
            float by = sWb[nt*8 + c4 + 1];
            #pragma unroll
            for (int mt = 0; mt < 2; mt++) {
                float v0 = acc[mt][nt][0] + bx;
                float v1 = acc[mt][nt][1] + by;
                float v2 = acc[mt][nt][2] + bx;
                float v3 = acc[mt][nt][3] + by;
                size_t r0 = (size_t)(tile*128 + rb + mt*16)*64 + nt*8 + c4;
                *(float2*)(g_wpre + r0)        = make_float2(v0, v1);
                *(float2*)(g_wpre + r0 + 512)  = make_float2(v2, v3);   // +8 rows
                s[nt].x += v0 + v2;  s[nt].y += v1 + v3;
                q2[nt].x = fmaf(v0, v0, fmaf(v2, v2, q2[nt].x));
                q2[nt].y = fmaf(v1, v1, fmaf(v3, v3, q2[nt].y));
            }
        }
    }

    // warp-reduce stats (lanes sharing lane&3 hold same columns)
    #pragma unroll
    for (int nt = 0; nt < 8; nt++) {
        #pragma unroll
        for (int d = 4; d <= 16; d <<= 1) {
            s[nt].x  += __shfl_xor_sync(0xFFFFFFFFu, s[nt].x,  d);
            s[nt].y  += __shfl_xor_sync(0xFFFFFFFFu, s[nt].y,  d);
            q2[nt].x += __shfl_xor_sync(0xFFFFFFFFu, q2[nt].x, d);
            q2[nt].y += __shfl_xor_sync(0xFFFFFFFFu, q2[nt].y, d);
        }
    }
    if ((lane >> 2) == 0) {
        #pragma unroll
        for (int nt = 0; nt < 8; nt++) {
            int c = nt*8 + c4;
            atomicAdd(&g_acc[128 + c],     (double)s[nt].x);
            atomicAdd(&g_acc[128 + c + 1], (double)s[nt].y);
            atomicAdd(&g_acc[192 + c],     (double)q2[nt].x);
            atomicAdd(&g_acc[192 + c + 1], (double)q2[nt].y);
        }
    }
}

// ---------------- pass D ----------------
__global__ void __launch_bounds__(128, 4) passD_kernel(
    const float* __restrict__ points,
    const int*   __restrict__ nb,
    const float* __restrict__ pw,
    const float* __restrict__ pb,
    float* __restrict__ out)
{
    __shared__ int   sIdx[8*16];
    __shared__ float sPts[8*16*4];

    const int tid = threadIdx.x;
    const int sub = tid >> 4;
    const int t   = tid & 15;
    const int d0  = 4*t;

    float w[12], br[4], sc1[4], sh1[4], sc2[4], sh2[4];
    #pragma unroll
    for (int j = 0; j < 4; j++) {
        w[j*3+0] = __ldg(pw + (d0+j)*3 + 0);
        w[j*3+1] = __ldg(pw + (d0+j)*3 + 1);
        w[j*3+2] = __ldg(pw + (d0+j)*3 + 2);
        br[j]    = __ldg(pb + d0 + j);
        sc1[j]   = g_stats[d0 + j];
        sh1[j]   = g_stats[64 + d0 + j];
        sc2[j]   = g_stats[128 + d0 + j];
        sh2[j]   = g_stats[192 + d0 + j];
    }

    for (int g = blockIdx.x; g < NPTS/8; g += gridDim.x) {
        const int n = g*8 + sub;
        __syncthreads();
        sIdx[sub*16 + t] = __ldg(nb + (size_t)n*KNB + t);
        __syncthreads();
        {
            int idx = sIdx[sub*16 + t];
            bool pad = (idx >= NPTS);
            sPts[(sub*16 + t)*4 + 0] = pad ? 1e6f : __ldg(points + (size_t)idx*3    );
            sPts[(sub*16 + t)*4 + 1] = pad ? 1e6f : __ldg(points + (size_t)idx*3 + 1);
            sPts[(sub*16 + t)*4 + 2] = pad ? 1e6f : __ldg(points + (size_t)idx*3 + 2);
        }
        __syncthreads();

        float4 wq[KNB];
        #pragma unroll
        for (int k = 0; k < KNB; k++) {
            float4 v = *(const float4*)(g_wpre + ((size_t)n*KNB + k)*DIM + d0);
            wq[k].x = fmaxf(fmaf(v.x, sc2[0], sh2[0]), 0.f);
            wq[k].y = fmaxf(fmaf(v.y, sc2[1], sh2[1]), 0.f);
            wq[k].z = fmaxf(fmaf(v.z, sc2[2], sh2[2]), 0.f);
            wq[k].w = fmaxf(fmaf(v.w, sc2[3], sh2[3]), 0.f);
        }
        float4 mx = wq[0];
        #pragma unroll
        for (int k = 1; k < KNB; k++) {
            mx.x = fmaxf(mx.x, wq[k].x); mx.y = fmaxf(mx.y, wq[k].y);
            mx.z = fmaxf(mx.z, wq[k].z); mx.w = fmaxf(mx.w, wq[k].w);
        }
        float4 se = make_float4(0.f,0.f,0.f,0.f);
        #pragma unroll
        for (int k = 0; k < KNB; k++) {
            wq[k].x = __expf(wq[k].x - mx.x); se.x += wq[k].x;
            wq[k].y = __expf(wq[k].y - mx.y); se.y += wq[k].y;
            wq[k].z = __expf(wq[k].z - mx.z); se.z += wq[k].z;
            wq[k].w = __expf(wq[k].w - mx.w); se.w += wq[k].w;
        }
        float4 inv;
        inv.x = __fdividef(1.f, se.x); inv.y = __fdividef(1.f, se.y);
        inv.z = __fdividef(1.f, se.z); inv.w = __fdividef(1.f, se.w);

        float4 att = make_float4(0.f,0.f,0.f,0.f);
        #pragma unroll
        for (int k = 0; k < KNB; k++) {
            int idx = sIdx[sub*16 + k];
            float x = sPts[(sub*16+k)*4], y = sPts[(sub*16+k)*4+1], z = sPts[(sub*16+k)*4+2];
            float pf0 = fmaxf(fmaf(fmaf(w[2],  z, fmaf(w[1],  y, fmaf(w[0],  x, br[0]))), sc1[0], sh1[0]), 0.f);
            float pf1 = fmaxf(fmaf(fmaf(w[5],  z, fmaf(w[4],  y, fmaf(w[3],  x, br[1]))), sc1[1], sh1[1]), 0.f);
            float pf2 = fmaxf(fmaf(fmaf(w[8],  z, fmaf(w[7],  y, fmaf(w[6],  x, br[2]))), sc1[2], sh1[2]), 0.f);
            float pf3 = fmaxf(fmaf(fmaf(w[11], z, fmaf(w[10], y, fmaf(w[9],  x, br[3]))), sc1[3], sh1[3]), 0.f);
            float4 vg = make_float4(0.f,0.f,0.f,0.f);
            if (idx < NPTS) vg = *(const float4*)(g_v + (size_t)idx*DIM + d0);
            att.x = fmaf(vg.x + pf0, wq[k].x * inv.x, att.x);
            att.y = fmaf(vg.y + pf1, wq[k].y * inv.y, att.y);
            att.z = fmaf(vg.z + pf2, wq[k].z * inv.z, att.z);
            att.w = fmaf(vg.w + pf3, wq[k].w * inv.w, att.w);
        }
        *(float4*)(out + (size_t)n*DIM + d0) = att;
    }
}

// ---------------- launch ----------------
extern "C" void kernel_launch(void* const* d_in, const int* in_sizes, int n_in,
                              void* d_out, int out_size)
{
    const float* points  = (const float*)d_in[0];
    const int*   nbrs    = (const int*)  d_in[1];
    const float* feats   = (const float*)d_in[2];
    const float* q_w = (const float*)d_in[3];  const float* q_b = (const float*)d_in[4];
    const float* k_w = (const float*)d_in[5];  const float* k_b = (const float*)d_in[6];
    const float* v_w = (const float*)d_in[7];  const float* v_b = (const float*)d_in[8];
    const float* p_w = (const float*)d_in[9];  const float* p_b = (const float*)d_in[10];
    const float* p_gamma = (const float*)d_in[11]; const float* p_beta = (const float*)d_in[12];
    const float* w_w = (const float*)d_in[13]; const float* w_b = (const float*)d_in[14];
    const float* w_gamma = (const float*)d_in[15]; const float* w_beta = (const float*)d_in[16];
    float* out = (float*)d_out;

    const int FE_SMEM = (12288 + 2304 + 192) * 4;
    cudaFuncSetAttribute(frontend_kernel, cudaFuncAttributeMaxDynamicSharedMemorySize, FE_SMEM);
    cudaFuncSetAttribute(passC_kernel,    cudaFuncAttributeMaxDynamicSharedMemorySize, PC_SMEM);

    zero_acc_kernel<<<1, 256>>>();
    frontend_kernel<<<FE_BLOCKS, FE_THREADS, FE_SMEM>>>(
        feats, q_w, q_b, k_w, k_b, v_w, v_b, points, nbrs, p_w, p_b);
    finalize_kernel<<<1, 64>>>(p_gamma, p_beta, 0);
    passC_kernel<<<PC_BLOCKS, 128, PC_SMEM>>>(points, nbrs, p_w, p_b, w_w, w_b);
    finalize_kernel<<<1, 64>>>(w_gamma, w_beta, 128);
    passD_kernel<<<1184, 128>>>(points, nbrs, p_w, p_b, out);
}